// round 15
// baseline (speedup 1.0000x reference)
#include <cuda_runtime.h>
#include <cuda_fp16.h>

// Problem constants
#define B   2
#define D   160
#define H   192
#define W   160
#define HW  (H * W)          // 30720
#define DHW (D * H * W)      // 4915200
#define NVOX (B * DHW)       // 9830400 per channel
#define CH  5
#define WIN 9
#define PAD 4
#define INV_N (1.0f / 729.0f)

// 4-half units (pass3)
#define W4    (W / 4)        // 40
#define HW4   (HW / 4)       // 7680
#define DHW4  (DHW / 4)      // 1228800
#define NVOX4 (NVOX / 4)     // 2457600

// float4 units (grad)
#define WQ   (W / 4)        // 40
#define HWQ  (HW / 4)       // 7680
#define DHWQ (DHW / 4)      // 1228800

// H segmentation for k_pass12
#define HSEG  64
#define NSEGH (H / HSEG)     // 3
#define NROWS (HSEG + 2 * PAD)  // 72 rows processed per block

// warp strips for k_pass12
#define NWARP 5              // W / 32

// D segmentation for k_pass3
#define SEG3  8
#define DSEG3 (D / SEG3)     // 20

// D segmentation for k_grad
#define GSEGD 4
#define GDSEG (D / GSEGD)    // 40

// Scratch — fp16 box-sums, uint2-typed for 8B alignment
__device__ uint2 g_bufH4[CH * NVOX4];
__device__ double g_acc[4] = {0.0, 0.0, 0.0, 0.0};  // self-resetting (finalize)

__device__ __forceinline__ void warp_reduce_atomic(float v, double* dst) {
#pragma unroll
    for (int off = 16; off > 0; off >>= 1)
        v += __shfl_down_sync(0xFFFFFFFFu, v, off);
    if ((threadIdx.x & 31) == 0) atomicAdd(dst, (double)v);
}

__device__ __forceinline__ float4 h4_to_f4(uint2 u) {
    const __half2 a = *reinterpret_cast<const __half2*>(&u.x);
    const __half2 b = *reinterpret_cast<const __half2*>(&u.y);
    const float2 fa = __half22float2(a);
    const float2 fb = __half22float2(b);
    return make_float4(fa.x, fa.y, fb.x, fb.y);
}

// ---------------------------------------------------------------------------
// Fused pass 1+2, WARP-AUTONOMOUS: each warp owns a 32-wide w-strip (+/-4 halo)
// and walks all rows independently. No __syncthreads — only __syncwarp.
// Double-buffered per-warp staging overlaps next-row LDG with current taps.
__global__ void __launch_bounds__(32 * NWARP, 8)
k_pass12(const float* __restrict__ F, const float* __restrict__ M) {
    __shared__ float2  stg[NWARP][2][40];        // [warp][buf][pos] 3.2KB
    __shared__ __half2 ring01[NWARP][WIN][32];   // (sumF, sumM)   5.76KB
    __shared__ __half2 ring23[NWARP][WIN][32];   // (sumF2, sumM2) 5.76KB
    __shared__ __half  ring4 [NWARP][WIN][32];   // sumFM          2.88KB

    __half2* __restrict__ bufH2 = (__half2*)g_bufH4;

    const int t    = threadIdx.x;
    const int wid  = t >> 5;
    const int lane = t & 31;
    const int w0   = wid << 5;                   // strip base w
    const int w    = w0 + lane;

    int blk = blockIdx.x;                        // over B*D*NSEGH = 960
    const int hs = blk % NSEGH; blk /= NSEGH;
    const int d  = blk % D;
    const int b  = blk / D;
    const int h0 = hs * HSEG;

    const size_t plane = (size_t)(b * D + d) * HW;
    const float* __restrict__ Fp = F + plane;
    const float* __restrict__ Mp = M + plane;
    const bool even = ((lane & 1) == 0);

    // load indices (strip-local, row-invariant)
    const int idxc = w0 - 4 + lane;              // main position lane
    const int idxh = w0 + 28 + lane;             // halo position (lanes 0..7)
    const bool vc = (idxc >= 0 && idxc < W);
    const bool vh = (lane < 8 && idxh < W);

    // Zero my warp's ring (warp-private; no block sync needed).
    const __half2 HZ = __floats2half2_rn(0.f, 0.f);
#pragma unroll
    for (int sl = 0; sl < WIN; sl++) {
        ring01[wid][sl][lane] = HZ;
        ring23[wid][sl][lane] = HZ;
        ring4 [wid][sl][lane] = __float2half_rn(0.f);
    }

    float fv, mv, fh, mh;

#define LDGROW(r_)                                                           \
    {                                                                        \
        fv = 0.f; mv = 0.f; fh = 0.f; mh = 0.f;                              \
        if ((r_) >= 0 && (r_) < H) {                                         \
            const int rb = (r_) * W;                                         \
            if (vc) { fv = Fp[rb + idxc]; mv = Mp[rb + idxc]; }              \
            if (vh) { fh = Fp[rb + idxh]; mh = Mp[rb + idxh]; }              \
        }                                                                    \
    }

#define STSROW(bu)                                                           \
    {                                                                        \
        stg[wid][bu][lane] = make_float2(fv, mv);                            \
        if (lane < 8) stg[wid][bu][32 + lane] = make_float2(fh, mh);         \
    }

    float s0 = 0.f, s1 = 0.f, s2 = 0.f, s3 = 0.f, s4 = 0.f;
    int slot = 0;

    // PROC from buffer bu: 9-tap W box at positions lane..lane+8, fp16 ring.
#define PROC(bu)                                                             \
    {                                                                        \
        float n0 = 0.f, n1 = 0.f, n2 = 0.f, n3 = 0.f, n4 = 0.f;              \
        _Pragma("unroll")                                                    \
        for (int k = 0; k < WIN; k++) {                                      \
            const float2 P = stg[wid][bu][lane + k];                         \
            n0 += P.x; n1 += P.y;                                            \
            n2 = fmaf(P.x, P.x, n2);                                         \
            n3 = fmaf(P.y, P.y, n3);                                         \
            n4 = fmaf(P.x, P.y, n4);                                         \
        }                                                                    \
        const __half2 h01 = __floats2half2_rn(n0, n1);                       \
        const __half2 h23 = __floats2half2_rn(n2, n3);                       \
        const __half  h4v = __float2half_rn(n4);                             \
        const float2 f01 = __half22float2(h01);                              \
        const float2 f23 = __half22float2(h23);                              \
        const float  f4  = __half2float(h4v);                                \
        const float2 g01 = __half22float2(ring01[wid][slot][lane]);          \
        const float2 g23 = __half22float2(ring23[wid][slot][lane]);          \
        const float  g4  = __half2float(ring4[wid][slot][lane]);             \
        s0 += f01.x - g01.x; s1 += f01.y - g01.y;                            \
        s2 += f23.x - g23.x; s3 += f23.y - g23.y;                            \
        s4 += f4 - g4;                                                       \
        ring01[wid][slot][lane] = h01;                                       \
        ring23[wid][slot][lane] = h23;                                       \
        ring4 [wid][slot][lane] = h4v;                                       \
        slot = (slot == WIN - 1) ? 0 : slot + 1;                             \
    }

    // Even lanes store packed {own, lane+1} half2 per channel.
#define EMIT(h_)                                                             \
    {                                                                        \
        const float t0 = __shfl_down_sync(0xFFFFFFFFu, s0, 1);               \
        const float t1 = __shfl_down_sync(0xFFFFFFFFu, s1, 1);               \
        const float t2 = __shfl_down_sync(0xFFFFFFFFu, s2, 1);               \
        const float t3 = __shfl_down_sync(0xFFFFFFFFu, s3, 1);               \
        const float t4 = __shfl_down_sync(0xFFFFFFFFu, s4, 1);               \
        if (even) {                                                          \
            const size_t o2 = (plane + (size_t)(h_) * W + w) >> 1;           \
            bufH2[((size_t)0 * NVOX >> 1) + o2] = __floats2half2_rn(s0, t0); \
            bufH2[((size_t)1 * NVOX >> 1) + o2] = __floats2half2_rn(s1, t1); \
            bufH2[((size_t)2 * NVOX >> 1) + o2] = __floats2half2_rn(s2, t2); \
            bufH2[((size_t)3 * NVOX >> 1) + o2] = __floats2half2_rn(s3, t3); \
            bufH2[((size_t)4 * NVOX >> 1) + o2] = __floats2half2_rn(s4, t4); \
        }                                                                    \
    }

    // Prologue: stage row h0-4 into buf 0.
    LDGROW(h0 - PAD);
    STSROW(0);
    __syncwarp();

#pragma unroll 2
    for (int ri = 0; ri < NROWS; ri++) {
        const int r = h0 - PAD + ri;
        if (ri < NROWS - 1) LDGROW(r + 1);       // prefetch overlaps taps

        PROC(ri & 1);
        if (ri >= 2 * PAD) EMIT(r - PAD);

        if (ri < NROWS - 1) {
            STSROW((ri + 1) & 1);
            __syncwarp();
        }
    }
#undef LDGROW
#undef STSROW
#undef PROC
#undef EMIT
}

// ---------------------------------------------------------------------------
// Pass 3: two-pointer D running window (unchanged).
__global__ void __launch_bounds__(160) k_pass3_cc() {
    const int t = threadIdx.x;
    const int qw = t % W4;
    const int hs = t / W4;                   // 0..3
    int blk = blockIdx.x;                    // over B * (H/4) * SEG3 = 768
    const int seg = blk % SEG3; blk /= SEG3;
    const int hq = blk % (H / 4);
    const int b  = blk / (H / 4);
    const int h  = hq * 4 + hs;
    const int d0 = seg * DSEG3;

    const size_t col = (size_t)b * DHW4 + (size_t)h * W4 + qw;

    float4 s[CH];
#pragma unroll
    for (int c = 0; c < CH; c++) s[c] = make_float4(0.f, 0.f, 0.f, 0.f);

#pragma unroll 1
    for (int i = 0; i < WIN; i++) {
        const int d = d0 - PAD + i;
        if (d >= 0) {
#pragma unroll
            for (int c = 0; c < CH; c++) {
                const float4 f = h4_to_f4(g_bufH4[(size_t)c * NVOX4 + col + (size_t)d * HW4]);
                s[c].x += f.x; s[c].y += f.y; s[c].z += f.z; s[c].w += f.w;
            }
        }
    }

    float local = 0.f;
#pragma unroll 2
    for (int u = 0; u < DSEG3; u++) {
        const int d = d0 + u;
#define CCC(comp)                                                            \
        {                                                                    \
            const float mf  = s[0].comp * INV_N;                             \
            const float mm  = s[1].comp * INV_N;                             \
            const float vF  = s[2].comp - mf * mf;                           \
            const float vM  = s[3].comp - mm * mm;                           \
            const float cov = s[4].comp - mf * mm;                           \
            local += (cov * cov) / (vF * vM + 1e-8f);                        \
        }
        CCC(x) CCC(y) CCC(z) CCC(w)
#undef CCC

        const int dn = d + PAD + 1;
        const int dm = d - PAD;
        if (dn < D) {
#pragma unroll
            for (int c = 0; c < CH; c++) {
                const float4 f = h4_to_f4(g_bufH4[(size_t)c * NVOX4 + col + (size_t)dn * HW4]);
                s[c].x += f.x; s[c].y += f.y; s[c].z += f.z; s[c].w += f.w;
            }
        }
        if (dm >= 0) {
#pragma unroll
            for (int c = 0; c < CH; c++) {
                const float4 f = h4_to_f4(g_bufH4[(size_t)c * NVOX4 + col + (size_t)dm * HW4]);
                s[c].x -= f.x; s[c].y -= f.y; s[c].z -= f.z; s[c].w -= f.w;
            }
        }
    }

    warp_reduce_atomic(local, &g_acc[0]);
}

// ---------------------------------------------------------------------------
// Flow gradient: d-walk with register reuse (side stream, unchanged).
__global__ void k_grad(const float* __restrict__ flow) {
    const float4* __restrict__ f4 = (const float4*)flow;
    const int t = threadIdx.x;
    const int qw = t % WQ;
    const int hs = t / WQ;                   // 0..3
    int blk = blockIdx.x;                    // over B*3 * (H/4) * GSEGD = 1152
    const int seg = blk % GSEGD; blk /= GSEGD;
    const int hq = blk % (H / 4);
    const int bc = blk / (H / 4);            // 0..5 (b*3 + c)
    const int h  = hq * 4 + hs;
    const int d0 = seg * GDSEG;

    const bool hasH = (h < H - 1);
    const bool hasW = (qw < WQ - 1);

    size_t base = (size_t)bc * DHWQ + (size_t)d0 * HWQ + (size_t)h * WQ + qw;
    float sdx = 0.f, sdy = 0.f, sdz = 0.f;
    float4 v = f4[base];

    const int dend = d0 + GDSEG;
#pragma unroll 4
    for (int d = d0; d < dend; d++) {
        sdz += fabsf(v.y - v.x) + fabsf(v.z - v.y) + fabsf(v.w - v.z);
        if (hasW) sdz += fabsf(flow[4 * base + 4] - v.w);
        if (hasH) {
            const float4 hn = f4[base + WQ];
            sdx += fabsf(hn.x - v.x) + fabsf(hn.y - v.y)
                 + fabsf(hn.z - v.z) + fabsf(hn.w - v.w);
        }
        if (d < D - 1) {
            const float4 dn = f4[base + HWQ];
            sdy += fabsf(dn.x - v.x) + fabsf(dn.y - v.y)
                 + fabsf(dn.z - v.z) + fabsf(dn.w - v.w);
            v = dn;
        }
        base += HWQ;
    }

    warp_reduce_atomic(sdx, &g_acc[1]);
    warp_reduce_atomic(sdy, &g_acc[2]);
    warp_reduce_atomic(sdz, &g_acc[3]);
}

// ---------------------------------------------------------------------------
// Finalize: emit outputs, then reset accumulators for the next replay.
__global__ void k_finalize(float* __restrict__ out) {
    const double L_sim = -(g_acc[0] / (double)NVOX);
    const double ndx = (double)B * 3.0 * D * (H - 1) * W;
    const double ndy = (double)B * 3.0 * (D - 1) * H * W;
    const double ndz = (double)B * 3.0 * D * H * (W - 1);
    const double L_reg = g_acc[1] / ndx + g_acc[2] / ndy + g_acc[3] / ndz;
    out[0] = (float)(L_sim + L_reg);
    out[1] = (float)L_sim;
    out[2] = (float)L_reg;
    g_acc[0] = 0.0; g_acc[1] = 0.0; g_acc[2] = 0.0; g_acc[3] = 0.0;
}

// ---------------------------------------------------------------------------
extern "C" void kernel_launch(void* const* d_in, const int* in_sizes, int n_in,
                              void* d_out, int out_size) {
    const float* I_fixed = (const float*)d_in[0];
    const float* I_moved = (const float*)d_in[1];
    const float* flow    = (const float*)d_in[2];
    float* out = (float*)d_out;

    static cudaStream_t s_side = 0;
    static cudaEvent_t ev_fork = 0, ev_join = 0;
    if (s_side == 0) {
        cudaStreamCreateWithFlags(&s_side, cudaStreamNonBlocking);
        cudaEventCreateWithFlags(&ev_fork, cudaEventDisableTiming);
        cudaEventCreateWithFlags(&ev_join, cudaEventDisableTiming);
    }

    // Fork: k_grad (reads flow only) runs concurrently with pass12/pass3.
    cudaEventRecord(ev_fork, 0);
    cudaStreamWaitEvent(s_side, ev_fork, 0);
    k_grad<<<B * 3 * (H / 4) * GSEGD, 160, 0, s_side>>>(flow);
    cudaEventRecord(ev_join, s_side);

    k_pass12<<<B * D * NSEGH, 32 * NWARP>>>(I_fixed, I_moved);
    k_pass3_cc<<<B * (H / 4) * SEG3, 160>>>();

    cudaStreamWaitEvent(0, ev_join, 0);
    k_finalize<<<1, 1>>>(out);
}

// round 16
// speedup vs baseline: 1.2286x; 1.2286x over previous
#include <cuda_runtime.h>
#include <cuda_fp16.h>

// Problem constants
#define B   2
#define D   160
#define H   192
#define W   160
#define HW  (H * W)          // 30720
#define DHW (D * H * W)      // 4915200
#define NVOX (B * DHW)       // 9830400 per channel
#define CH  5
#define WIN 9
#define PAD 4
#define INV_N (1.0f / 729.0f)

// 4-half units (pass3)
#define W4    (W / 4)        // 40
#define HW4   (HW / 4)       // 7680
#define DHW4  (DHW / 4)      // 1228800
#define NVOX4 (NVOX / 4)     // 2457600

// float4 units (grad)
#define WQ   (W / 4)        // 40
#define HWQ  (HW / 4)       // 7680
#define DHWQ (DHW / 4)      // 1228800

// H segmentation for k_pass12: 72 rows per block = 8 chunks of 9 rows
#define HSEG  64
#define NSEGH (H / HSEG)     // 3
#define CROWS 9              // rows per chunk (== ring period -> literal slots)
#define NCHUNK 8             // 72 / 9

// D segmentation for k_pass3
#define SEG3  8
#define DSEG3 (D / SEG3)     // 20

// D segmentation for k_grad
#define GSEGD 4
#define GDSEG (D / GSEGD)    // 40

// Scratch — fp16 box-sums, uint2-typed for 8B alignment
__device__ uint2 g_bufH4[CH * NVOX4];
__device__ double g_acc[4] = {0.0, 0.0, 0.0, 0.0};  // self-resetting (finalize)

__device__ __forceinline__ void warp_reduce_atomic(float v, double* dst) {
#pragma unroll
    for (int off = 16; off > 0; off >>= 1)
        v += __shfl_down_sync(0xFFFFFFFFu, v, off);
    if ((threadIdx.x & 31) == 0) atomicAdd(dst, (double)v);
}

__device__ __forceinline__ float4 h4_to_f4(uint2 u) {
    const __half2 a = *reinterpret_cast<const __half2*>(&u.x);
    const __half2 b = *reinterpret_cast<const __half2*>(&u.y);
    const float2 fa = __half22float2(a);
    const float2 fb = __half22float2(b);
    return make_float4(fa.x, fa.y, fb.x, fb.y);
}

// ---------------------------------------------------------------------------
// Fused pass 1+2: 9-row chunks (ring period) -> REGISTER ring with literal
// slots; 8 barriers/block; 18-deep LDG prefetch per chunk.
__global__ void __launch_bounds__(160)
k_pass12(const float* __restrict__ F, const float* __restrict__ M) {
    __shared__ float2 stg[2][CROWS][W + 2 * PAD];  // (f,m) pairs, 24.2KB

    __half2* __restrict__ bufH2 = (__half2*)g_bufH4;

    const int w = threadIdx.x;
    int blk = blockIdx.x;                        // over B*D*NSEGH = 960
    const int hs = blk % NSEGH; blk /= NSEGH;
    const int d  = blk % D;
    const int b  = blk / D;
    const int h0 = hs * HSEG;

    const size_t plane = (size_t)(b * D + d) * HW;
    const float* __restrict__ Fp = F + plane;
    const float* __restrict__ Mp = M + plane;
    const bool even = ((w & 1) == 0);

    // Register-resident ring (fp16-packed ch0..3, fp32 ch4).
    __half2 r01[CROWS], r23[CROWS];
    float   r4[CROWS];
    const __half2 HZ = __floats2half2_rn(0.f, 0.f);
#pragma unroll
    for (int i = 0; i < CROWS; i++) { r01[i] = HZ; r23[i] = HZ; r4[i] = 0.f; }

    // Zero staging halos once.
    if (w < PAD) {
#pragma unroll
        for (int bu = 0; bu < 2; bu++)
#pragma unroll
            for (int r = 0; r < CROWS; r++) {
                stg[bu][r][w] = make_float2(0.f, 0.f);
                stg[bu][r][w + W + PAD] = make_float2(0.f, 0.f);
            }
    }

    float rf[CROWS], rm[CROWS];

    // Load 9 rows of chunk jj into registers (18 independent LDGs).
#define LDGCHUNK(jj)                                                         \
    {                                                                        \
        _Pragma("unroll")                                                    \
        for (int i = 0; i < CROWS; i++) {                                    \
            const int r_ = h0 - PAD + CROWS * (jj) + i;                      \
            const bool v_ = (r_ >= 0 && r_ < H);                             \
            rf[i] = v_ ? Fp[r_ * W + w] : 0.f;                               \
            rm[i] = v_ ? Mp[r_ * W + w] : 0.f;                               \
        }                                                                    \
    }

#define STSCHUNK(bu)                                                         \
    {                                                                        \
        _Pragma("unroll")                                                    \
        for (int i = 0; i < CROWS; i++)                                      \
            stg[bu][i][w + PAD] = make_float2(rf[i], rm[i]);                 \
    }

    float s0 = 0.f, s1 = 0.f, s2 = 0.f, s3 = 0.f, s4 = 0.f;

    // PROC staged row i (slot == i, literal): 9-tap W box + register ring.
#define PROC(bu, i)                                                          \
    {                                                                        \
        float n0 = 0.f, n1 = 0.f, n2 = 0.f, n3 = 0.f, n4 = 0.f;              \
        _Pragma("unroll")                                                    \
        for (int k = 0; k < WIN; k++) {                                      \
            const float2 P = stg[bu][i][w + k];                              \
            n0 += P.x; n1 += P.y;                                            \
            n2 = fmaf(P.x, P.x, n2);                                         \
            n3 = fmaf(P.y, P.y, n3);                                         \
            n4 = fmaf(P.x, P.y, n4);                                         \
        }                                                                    \
        const __half2 h01 = __floats2half2_rn(n0, n1);                       \
        const __half2 h23 = __floats2half2_rn(n2, n3);                       \
        const float2 f01 = __half22float2(h01);                              \
        const float2 f23 = __half22float2(h23);                              \
        const float2 g01 = __half22float2(r01[i]);                           \
        const float2 g23 = __half22float2(r23[i]);                           \
        s0 += f01.x - g01.x; s1 += f01.y - g01.y;                            \
        s2 += f23.x - g23.x; s3 += f23.y - g23.y;                            \
        s4 += n4 - r4[i];                                                    \
        r01[i] = h01; r23[i] = h23; r4[i] = n4;                              \
    }

    // Even lanes store packed {own, lane+1} half2 per channel.
#define EMIT(h_)                                                             \
    {                                                                        \
        const float t0 = __shfl_down_sync(0xFFFFFFFFu, s0, 1);               \
        const float t1 = __shfl_down_sync(0xFFFFFFFFu, s1, 1);               \
        const float t2 = __shfl_down_sync(0xFFFFFFFFu, s2, 1);               \
        const float t3 = __shfl_down_sync(0xFFFFFFFFu, s3, 1);               \
        const float t4 = __shfl_down_sync(0xFFFFFFFFu, s4, 1);               \
        if (even) {                                                          \
            const size_t o2 = (plane + (size_t)(h_) * W + w) >> 1;           \
            bufH2[((size_t)0 * NVOX >> 1) + o2] = __floats2half2_rn(s0, t0); \
            bufH2[((size_t)1 * NVOX >> 1) + o2] = __floats2half2_rn(s1, t1); \
            bufH2[((size_t)2 * NVOX >> 1) + o2] = __floats2half2_rn(s2, t2); \
            bufH2[((size_t)3 * NVOX >> 1) + o2] = __floats2half2_rn(s3, t3); \
            bufH2[((size_t)4 * NVOX >> 1) + o2] = __floats2half2_rn(s4, t4); \
        }                                                                    \
    }

    // Prologue: stage chunk 0 (rows h0-4 .. h0+4) into buf 0.
    LDGCHUNK(0);
    STSCHUNK(0);
    __syncthreads();

    // Chunk 0: build window; only row i=8 completes an output (h0).
    LDGCHUNK(1);
    PROC(0, 0) PROC(0, 1) PROC(0, 2) PROC(0, 3) PROC(0, 4)
    PROC(0, 5) PROC(0, 6) PROC(0, 7) PROC(0, 8) EMIT(h0);
    STSCHUNK(1);
    __syncthreads();

    // Chunks 1..7: each PROC completes an output row.
#pragma unroll 1
    for (int j = 1; j < NCHUNK; j++) {
        if (j < NCHUNK - 1) LDGCHUNK(j + 1);     // prefetch overlaps PROC

        const int bu = j & 1;
        const int hb = h0 + CROWS * j - 8;       // h of PROC(bu,0)'s output
        PROC(bu, 0) EMIT(hb + 0);
        PROC(bu, 1) EMIT(hb + 1);
        PROC(bu, 2) EMIT(hb + 2);
        PROC(bu, 3) EMIT(hb + 3);
        PROC(bu, 4) EMIT(hb + 4);
        PROC(bu, 5) EMIT(hb + 5);
        PROC(bu, 6) EMIT(hb + 6);
        PROC(bu, 7) EMIT(hb + 7);
        PROC(bu, 8) EMIT(hb + 8);

        if (j < NCHUNK - 1) {
            STSCHUNK(bu ^ 1);
            __syncthreads();
        }
    }
#undef LDGCHUNK
#undef STSCHUNK
#undef PROC
#undef EMIT
}

// ---------------------------------------------------------------------------
// Pass 3: two-pointer D running window (unchanged from R14 best).
__global__ void __launch_bounds__(160) k_pass3_cc() {
    const int t = threadIdx.x;
    const int qw = t % W4;
    const int hs = t / W4;                   // 0..3
    int blk = blockIdx.x;                    // over B * (H/4) * SEG3 = 768
    const int seg = blk % SEG3; blk /= SEG3;
    const int hq = blk % (H / 4);
    const int b  = blk / (H / 4);
    const int h  = hq * 4 + hs;
    const int d0 = seg * DSEG3;

    const size_t col = (size_t)b * DHW4 + (size_t)h * W4 + qw;

    float4 s[CH];
#pragma unroll
    for (int c = 0; c < CH; c++) s[c] = make_float4(0.f, 0.f, 0.f, 0.f);

#pragma unroll 1
    for (int i = 0; i < WIN; i++) {
        const int d = d0 - PAD + i;
        if (d >= 0) {
#pragma unroll
            for (int c = 0; c < CH; c++) {
                const float4 f = h4_to_f4(g_bufH4[(size_t)c * NVOX4 + col + (size_t)d * HW4]);
                s[c].x += f.x; s[c].y += f.y; s[c].z += f.z; s[c].w += f.w;
            }
        }
    }

    float local = 0.f;
#pragma unroll 2
    for (int u = 0; u < DSEG3; u++) {
        const int d = d0 + u;
#define CCC(comp)                                                            \
        {                                                                    \
            const float mf  = s[0].comp * INV_N;                             \
            const float mm  = s[1].comp * INV_N;                             \
            const float vF  = s[2].comp - mf * mf;                           \
            const float vM  = s[3].comp - mm * mm;                           \
            const float cov = s[4].comp - mf * mm;                           \
            local += (cov * cov) / (vF * vM + 1e-8f);                        \
        }
        CCC(x) CCC(y) CCC(z) CCC(w)
#undef CCC

        const int dn = d + PAD + 1;
        const int dm = d - PAD;
        if (dn < D) {
#pragma unroll
            for (int c = 0; c < CH; c++) {
                const float4 f = h4_to_f4(g_bufH4[(size_t)c * NVOX4 + col + (size_t)dn * HW4]);
                s[c].x += f.x; s[c].y += f.y; s[c].z += f.z; s[c].w += f.w;
            }
        }
        if (dm >= 0) {
#pragma unroll
            for (int c = 0; c < CH; c++) {
                const float4 f = h4_to_f4(g_bufH4[(size_t)c * NVOX4 + col + (size_t)dm * HW4]);
                s[c].x -= f.x; s[c].y -= f.y; s[c].z -= f.z; s[c].w -= f.w;
            }
        }
    }

    warp_reduce_atomic(local, &g_acc[0]);
}

// ---------------------------------------------------------------------------
// Flow gradient: d-walk with register reuse (side stream, unchanged).
__global__ void k_grad(const float* __restrict__ flow) {
    const float4* __restrict__ f4 = (const float4*)flow;
    const int t = threadIdx.x;
    const int qw = t % WQ;
    const int hs = t / WQ;                   // 0..3
    int blk = blockIdx.x;                    // over B*3 * (H/4) * GSEGD = 1152
    const int seg = blk % GSEGD; blk /= GSEGD;
    const int hq = blk % (H / 4);
    const int bc = blk / (H / 4);            // 0..5 (b*3 + c)
    const int h  = hq * 4 + hs;
    const int d0 = seg * GDSEG;

    const bool hasH = (h < H - 1);
    const bool hasW = (qw < WQ - 1);

    size_t base = (size_t)bc * DHWQ + (size_t)d0 * HWQ + (size_t)h * WQ + qw;
    float sdx = 0.f, sdy = 0.f, sdz = 0.f;
    float4 v = f4[base];

    const int dend = d0 + GDSEG;
#pragma unroll 4
    for (int d = d0; d < dend; d++) {
        sdz += fabsf(v.y - v.x) + fabsf(v.z - v.y) + fabsf(v.w - v.z);
        if (hasW) sdz += fabsf(flow[4 * base + 4] - v.w);
        if (hasH) {
            const float4 hn = f4[base + WQ];
            sdx += fabsf(hn.x - v.x) + fabsf(hn.y - v.y)
                 + fabsf(hn.z - v.z) + fabsf(hn.w - v.w);
        }
        if (d < D - 1) {
            const float4 dn = f4[base + HWQ];
            sdy += fabsf(dn.x - v.x) + fabsf(dn.y - v.y)
                 + fabsf(dn.z - v.z) + fabsf(dn.w - v.w);
            v = dn;
        }
        base += HWQ;
    }

    warp_reduce_atomic(sdx, &g_acc[1]);
    warp_reduce_atomic(sdy, &g_acc[2]);
    warp_reduce_atomic(sdz, &g_acc[3]);
}

// ---------------------------------------------------------------------------
// Finalize: emit outputs, then reset accumulators for the next replay.
__global__ void k_finalize(float* __restrict__ out) {
    const double L_sim = -(g_acc[0] / (double)NVOX);
    const double ndx = (double)B * 3.0 * D * (H - 1) * W;
    const double ndy = (double)B * 3.0 * (D - 1) * H * W;
    const double ndz = (double)B * 3.0 * D * H * (W - 1);
    const double L_reg = g_acc[1] / ndx + g_acc[2] / ndy + g_acc[3] / ndz;
    out[0] = (float)(L_sim + L_reg);
    out[1] = (float)L_sim;
    out[2] = (float)L_reg;
    g_acc[0] = 0.0; g_acc[1] = 0.0; g_acc[2] = 0.0; g_acc[3] = 0.0;
}

// ---------------------------------------------------------------------------
extern "C" void kernel_launch(void* const* d_in, const int* in_sizes, int n_in,
                              void* d_out, int out_size) {
    const float* I_fixed = (const float*)d_in[0];
    const float* I_moved = (const float*)d_in[1];
    const float* flow    = (const float*)d_in[2];
    float* out = (float*)d_out;

    static cudaStream_t s_side = 0;
    static cudaEvent_t ev_fork = 0, ev_join = 0;
    if (s_side == 0) {
        cudaStreamCreateWithFlags(&s_side, cudaStreamNonBlocking);
        cudaEventCreateWithFlags(&ev_fork, cudaEventDisableTiming);
        cudaEventCreateWithFlags(&ev_join, cudaEventDisableTiming);
    }

    // Fork: k_grad (reads flow only) runs concurrently with pass12/pass3.
    cudaEventRecord(ev_fork, 0);
    cudaStreamWaitEvent(s_side, ev_fork, 0);
    k_grad<<<B * 3 * (H / 4) * GSEGD, 160, 0, s_side>>>(flow);
    cudaEventRecord(ev_join, s_side);

    k_pass12<<<B * D * NSEGH, 160>>>(I_fixed, I_moved);
    k_pass3_cc<<<B * (H / 4) * SEG3, 160>>>();

    cudaStreamWaitEvent(0, ev_join, 0);
    k_finalize<<<1, 1>>>(out);
}